// round 14
// baseline (speedup 1.0000x reference)
#include <cuda_runtime.h>

#define BB 4096
#define DD 1024
#define THREADS 256
#define WARPS_PER_BLOCK (THREADS / 32)
#define NBLOCKS (BB / WARPS_PER_BLOCK)    // 512
#define CHUNKS (DD / 4 / 32)              // 8 float4 chunks per lane per row
#define EPSF 1e-8f
#define MARGIN 0.2f
#define NACC 11

__global__ void init_out_kernel(float* out) {
    out[0] = 0.0f;
}

__global__ __launch_bounds__(THREADS, 2)   // 128-reg budget: room for TWO full
                                           // 6-load batches in flight (MLP=12)
void contrastive_kernel(const float* __restrict__ img,
                        const float* __restrict__ txt,
                        const int* __restrict__ cand_img,
                        const int* __restrict__ cand_txt,
                        float* __restrict__ out) {
    const int tid  = threadIdx.x;
    const int warp = tid >> 5;
    const int lane = tid & 31;
    const int b    = blockIdx.x * WARPS_PER_BLOCK + warp;   // one warp per row

    const int ct0 = cand_txt[2 * b + 0];
    const int ct1 = cand_txt[2 * b + 1];
    const int ci0 = cand_img[2 * b + 0];
    const int ci1 = cand_img[2 * b + 1];

    const float4* ib  = (const float4*)(img + (size_t)b   * DD) + lane;
    const float4* tb  = (const float4*)(txt + (size_t)b   * DD) + lane;
    const float4* tc0 = (const float4*)(txt + (size_t)ct0 * DD) + lane;
    const float4* tc1 = (const float4*)(txt + (size_t)ct1 * DD) + lane;
    const float4* ic0 = (const float4*)(img + (size_t)ci0 * DD) + lane;
    const float4* ic1 = (const float4*)(img + (size_t)ci1 * DD) + lane;

    // 0: |img_b|^2   1: |txt_b|^2   2: dot(img_b, txt_b)
    // 3: dot(img_b, txt_c0)  4: |txt_c0|^2
    // 5: dot(img_b, txt_c1)  6: |txt_c1|^2
    // 7: dot(txt_b, img_e0)  8: |img_e0|^2
    // 9: dot(txt_b, img_e1) 10: |img_e1|^2
    float acc[NACC];
    #pragma unroll
    for (int a = 0; a < NACC; a++) acc[a] = 0.0f;

    // double-batch software pipeline with NAMED register rotation:
    // batch c+1's 6 loads issue before batch c's FMAs consume.
    float4 aI, aT, aT0, aT1, aI0, aI1;    // current batch
    aI  = ib[0];
    aT  = tb[0];
    aT0 = tc0[0];
    aT1 = tc1[0];
    aI0 = ic0[0];
    aI1 = ic1[0];

    #pragma unroll
    for (int c = 0; c < CHUNKS; c++) {
        float4 nI, nT, nT0, nT1, nI0, nI1;   // next batch (prefetch)
        if (c + 1 < CHUNKS) {
            const int o = (c + 1) * 32;
            nI  = ib[o];
            nT  = tb[o];
            nT0 = tc0[o];
            nT1 = tc1[o];
            nI0 = ic0[o];
            nI1 = ic1[o];
        }

        acc[0]  += aI.x*aI.x  + aI.y*aI.y  + aI.z*aI.z  + aI.w*aI.w;
        acc[1]  += aT.x*aT.x  + aT.y*aT.y  + aT.z*aT.z  + aT.w*aT.w;
        acc[2]  += aI.x*aT.x  + aI.y*aT.y  + aI.z*aT.z  + aI.w*aT.w;
        acc[3]  += aI.x*aT0.x + aI.y*aT0.y + aI.z*aT0.z + aI.w*aT0.w;
        acc[4]  += aT0.x*aT0.x+ aT0.y*aT0.y+ aT0.z*aT0.z+ aT0.w*aT0.w;
        acc[5]  += aI.x*aT1.x + aI.y*aT1.y + aI.z*aT1.z + aI.w*aT1.w;
        acc[6]  += aT1.x*aT1.x+ aT1.y*aT1.y+ aT1.z*aT1.z+ aT1.w*aT1.w;
        acc[7]  += aT.x*aI0.x + aT.y*aI0.y + aT.z*aI0.z + aT.w*aI0.w;
        acc[8]  += aI0.x*aI0.x+ aI0.y*aI0.y+ aI0.z*aI0.z+ aI0.w*aI0.w;
        acc[9]  += aT.x*aI1.x + aT.y*aI1.y + aT.z*aI1.z + aT.w*aI1.w;
        acc[10] += aI1.x*aI1.x+ aI1.y*aI1.y+ aI1.z*aI1.z+ aI1.w*aI1.w;

        if (c + 1 < CHUNKS) {
            aI  = nI;
            aT  = nT;
            aT0 = nT0;
            aT1 = nT1;
            aI0 = nI0;
            aI1 = nI1;
        }
    }

    // single warp-level reduction per row
    #pragma unroll
    for (int a = 0; a < NACC; a++) {
        float x = acc[a];
        #pragma unroll
        for (int off = 16; off > 0; off >>= 1)
            x += __shfl_xor_sync(0xFFFFFFFFu, x, off);
        acc[a] = x;
    }

    __shared__ float sloss[WARPS_PER_BLOCK];

    if (lane == 0) {
        const float ni    = sqrtf(acc[0]);   // |img_b|
        const float nt    = sqrtf(acc[1]);   // |txt_b|
        const float nprod = ni * nt;

        const float sim      = acc[2] / nprod;                      // unclamped
        const float pos_dist = 1.0f - acc[2] / fmaxf(nprod, EPSF);  // clamped

        const float dT0 = 1.0f - acc[3] / fmaxf(ni * sqrtf(acc[4]), EPSF);
        const float dT1 = 1.0f - acc[5] / fmaxf(ni * sqrtf(acc[6]), EPSF);
        const float i2t_neg = fminf(dT0, dT1);   // `d1<=d0` tie-break == min

        const float dI0 = 1.0f - acc[7] / fmaxf(nt * sqrtf(acc[8]),  EPSF);
        const float dI1 = 1.0f - acc[9] / fmaxf(nt * sqrtf(acc[10]), EPSF);
        const float t2i_neg = fminf(dI0, dI1);

        const float i2t_trip = fmaxf(pos_dist - i2t_neg + MARGIN, 0.0f);
        const float t2i_trip = fmaxf(pos_dist - t2i_neg + MARGIN, 0.0f);

        // outputs: [loss, i2t_cosine(B), t2i_cosine(B)]; cosines identical pair
        out[1 + b]      = sim;
        out[1 + BB + b] = sim;
        sloss[warp] = (i2t_trip + t2i_trip) * (1.0f / (float)BB);
    }

    __syncthreads();
    if (tid == 0) {
        float s = 0.0f;
        #pragma unroll
        for (int w = 0; w < WARPS_PER_BLOCK; w++) s += sloss[w];
        atomicAdd(out, s);   // 512 same-address atomics total
    }
}

extern "C" void kernel_launch(void* const* d_in, const int* in_sizes, int n_in,
                              void* d_out, int out_size) {
    const float* img      = (const float*)d_in[0];
    const float* txt      = (const float*)d_in[1];
    // d_in[2] = labels (identity anchors, unused), d_in[3] = locations (unused)
    const int*   cand_img = (const int*)d_in[4];
    const int*   cand_txt = (const int*)d_in[5];
    float* out = (float*)d_out;

    init_out_kernel<<<1, 1>>>(out);
    contrastive_kernel<<<NBLOCKS, THREADS>>>(img, txt, cand_img, cand_txt, out);
}

// round 15
// speedup vs baseline: 1.0840x; 1.0840x over previous
#include <cuda_runtime.h>

#define BB 4096
#define DD 1024
#define THREADS 256
#define WARPS_PER_BLOCK (THREADS / 32)
#define NBLOCKS (BB / WARPS_PER_BLOCK)    // 512
#define CHUNKS (DD / 4 / 32)              // 8 float4 chunks per lane per row
#define EPSF 1e-8f
#define MARGIN 0.2f
#define NACC 11

__global__ void init_out_kernel(float* out) {
    out[0] = 0.0f;
}

__global__ __launch_bounds__(THREADS, 4)   // 64-reg budget: warm-replay optimum (R5)
void contrastive_kernel(const float* __restrict__ img,
                        const float* __restrict__ txt,
                        const int* __restrict__ cand_img,
                        const int* __restrict__ cand_txt,
                        float* __restrict__ out) {
    const int tid  = threadIdx.x;
    const int warp = tid >> 5;
    const int lane = tid & 31;
    const int b    = blockIdx.x * WARPS_PER_BLOCK + warp;   // one warp per row

    // candidate indices (converged scalar loads broadcast in L1)
    const int ct0 = cand_txt[2 * b + 0];
    const int ct1 = cand_txt[2 * b + 1];
    const int ci0 = cand_img[2 * b + 0];
    const int ci1 = cand_img[2 * b + 1];

    const float4* ib  = (const float4*)(img + (size_t)b   * DD);
    const float4* tb  = (const float4*)(txt + (size_t)b   * DD);
    const float4* tc0 = (const float4*)(txt + (size_t)ct0 * DD);
    const float4* tc1 = (const float4*)(txt + (size_t)ct1 * DD);
    const float4* ic0 = (const float4*)(img + (size_t)ci0 * DD);
    const float4* ic1 = (const float4*)(img + (size_t)ci1 * DD);

    // 0: |img_b|^2   1: |txt_b|^2   2: dot(img_b, txt_b)
    // 3: dot(img_b, txt_c0)  4: |txt_c0|^2
    // 5: dot(img_b, txt_c1)  6: |txt_c1|^2
    // 7: dot(txt_b, img_e0)  8: |img_e0|^2
    // 9: dot(txt_b, img_e1) 10: |img_e1|^2
    float acc[NACC];
    #pragma unroll
    for (int a = 0; a < NACC; a++) acc[a] = 0.0f;

    #pragma unroll
    for (int c = 0; c < CHUNKS; c++) {
        const int o = c * 32 + lane;
        float4 vi  = ib[o];
        float4 vt  = tb[o];
        float4 vt0 = tc0[o];
        float4 vt1 = tc1[o];
        float4 vi0 = ic0[o];
        float4 vi1 = ic1[o];

        acc[0]  += vi.x*vi.x  + vi.y*vi.y  + vi.z*vi.z  + vi.w*vi.w;
        acc[1]  += vt.x*vt.x  + vt.y*vt.y  + vt.z*vt.z  + vt.w*vt.w;
        acc[2]  += vi.x*vt.x  + vi.y*vt.y  + vi.z*vt.z  + vi.w*vt.w;
        acc[3]  += vi.x*vt0.x + vi.y*vt0.y + vi.z*vt0.z + vi.w*vt0.w;
        acc[4]  += vt0.x*vt0.x+ vt0.y*vt0.y+ vt0.z*vt0.z+ vt0.w*vt0.w;
        acc[5]  += vi.x*vt1.x + vi.y*vt1.y + vi.z*vt1.z + vi.w*vt1.w;
        acc[6]  += vt1.x*vt1.x+ vt1.y*vt1.y+ vt1.z*vt1.z+ vt1.w*vt1.w;
        acc[7]  += vt.x*vi0.x + vt.y*vi0.y + vt.z*vi0.z + vt.w*vi0.w;
        acc[8]  += vi0.x*vi0.x+ vi0.y*vi0.y+ vi0.z*vi0.z+ vi0.w*vi0.w;
        acc[9]  += vt.x*vi1.x + vt.y*vi1.y + vt.z*vi1.z + vt.w*vi1.w;
        acc[10] += vi1.x*vi1.x+ vi1.y*vi1.y+ vi1.z*vi1.z+ vi1.w*vi1.w;
    }

    // single warp-level reduction per row
    #pragma unroll
    for (int a = 0; a < NACC; a++) {
        float x = acc[a];
        #pragma unroll
        for (int off = 16; off > 0; off >>= 1)
            x += __shfl_xor_sync(0xFFFFFFFFu, x, off);
        acc[a] = x;
    }

    if (lane == 0) {
        const float ni    = sqrtf(acc[0]);   // |img_b|
        const float nt    = sqrtf(acc[1]);   // |txt_b|
        const float nprod = ni * nt;

        const float sim      = acc[2] / nprod;                      // unclamped
        const float pos_dist = 1.0f - acc[2] / fmaxf(nprod, EPSF);  // clamped

        const float dT0 = 1.0f - acc[3] / fmaxf(ni * sqrtf(acc[4]), EPSF);
        const float dT1 = 1.0f - acc[5] / fmaxf(ni * sqrtf(acc[6]), EPSF);
        const float i2t_neg = fminf(dT0, dT1);   // `d1<=d0` tie-break == min

        const float dI0 = 1.0f - acc[7] / fmaxf(nt * sqrtf(acc[8]),  EPSF);
        const float dI1 = 1.0f - acc[9] / fmaxf(nt * sqrtf(acc[10]), EPSF);
        const float t2i_neg = fminf(dI0, dI1);

        const float i2t_trip = fmaxf(pos_dist - i2t_neg + MARGIN, 0.0f);
        const float t2i_trip = fmaxf(pos_dist - t2i_neg + MARGIN, 0.0f);

        // outputs: [loss, i2t_cosine(B), t2i_cosine(B)]; cosines identical pair
        out[1 + b]      = sim;
        out[1 + BB + b] = sim;
        // direct per-row loss contribution: REDG, no barrier, no smem
        atomicAdd(out, (i2t_trip + t2i_trip) * (1.0f / (float)BB));
    }
}

extern "C" void kernel_launch(void* const* d_in, const int* in_sizes, int n_in,
                              void* d_out, int out_size) {
    const float* img      = (const float*)d_in[0];
    const float* txt      = (const float*)d_in[1];
    // d_in[2] = labels (identity anchors, unused), d_in[3] = locations (unused)
    const int*   cand_img = (const int*)d_in[4];
    const int*   cand_txt = (const int*)d_in[5];
    float* out = (float*)d_out;

    init_out_kernel<<<1, 1>>>(out);
    contrastive_kernel<<<NBLOCKS, THREADS>>>(img, txt, cand_img, cand_txt, out);
}

// round 16
// speedup vs baseline: 1.4561x; 1.3434x over previous
#include <cuda_runtime.h>

#define BB 4096
#define DD 1024
#define THREADS 256
#define WARPS_PER_BLOCK (THREADS / 32)
#define NBLOCKS (BB / WARPS_PER_BLOCK)    // 512
#define CHUNKS (DD / 4 / 32)              // 8 float4 chunks per lane per row
#define EPSF 1e-8f
#define MARGIN 0.2f
#define NACC 11

__global__ void init_out_kernel(float* out) {
    out[0] = 0.0f;
    // allow the dependent main kernel to launch as soon as this completes
    cudaTriggerProgrammaticLaunchCompletion();
}

__global__ __launch_bounds__(THREADS, 4)   // 64-reg budget: warm-replay optimum (R5)
void contrastive_kernel(const float* __restrict__ img,
                        const float* __restrict__ txt,
                        const int* __restrict__ cand_img,
                        const int* __restrict__ cand_txt,
                        float* __restrict__ out) {
    const int tid  = threadIdx.x;
    const int warp = tid >> 5;
    const int lane = tid & 31;
    const int b    = blockIdx.x * WARPS_PER_BLOCK + warp;   // one warp per row

    // candidate indices (converged scalar loads broadcast in L1)
    const int ct0 = cand_txt[2 * b + 0];
    const int ct1 = cand_txt[2 * b + 1];
    const int ci0 = cand_img[2 * b + 0];
    const int ci1 = cand_img[2 * b + 1];

    const float4* ib  = (const float4*)(img + (size_t)b   * DD);
    const float4* tb  = (const float4*)(txt + (size_t)b   * DD);
    const float4* tc0 = (const float4*)(txt + (size_t)ct0 * DD);
    const float4* tc1 = (const float4*)(txt + (size_t)ct1 * DD);
    const float4* ic0 = (const float4*)(img + (size_t)ci0 * DD);
    const float4* ic1 = (const float4*)(img + (size_t)ci1 * DD);

    // 0: |img_b|^2   1: |txt_b|^2   2: dot(img_b, txt_b)
    // 3: dot(img_b, txt_c0)  4: |txt_c0|^2
    // 5: dot(img_b, txt_c1)  6: |txt_c1|^2
    // 7: dot(txt_b, img_e0)  8: |img_e0|^2
    // 9: dot(txt_b, img_e1) 10: |img_e1|^2
    float acc[NACC];
    #pragma unroll
    for (int a = 0; a < NACC; a++) acc[a] = 0.0f;

    #pragma unroll
    for (int c = 0; c < CHUNKS; c++) {
        const int o = c * 32 + lane;
        float4 vi  = ib[o];
        float4 vt  = tb[o];
        float4 vt0 = tc0[o];
        float4 vt1 = tc1[o];
        float4 vi0 = ic0[o];
        float4 vi1 = ic1[o];

        acc[0]  += vi.x*vi.x  + vi.y*vi.y  + vi.z*vi.z  + vi.w*vi.w;
        acc[1]  += vt.x*vt.x  + vt.y*vt.y  + vt.z*vt.z  + vt.w*vt.w;
        acc[2]  += vi.x*vt.x  + vi.y*vt.y  + vi.z*vt.z  + vi.w*vt.w;
        acc[3]  += vi.x*vt0.x + vi.y*vt0.y + vi.z*vt0.z + vi.w*vt0.w;
        acc[4]  += vt0.x*vt0.x+ vt0.y*vt0.y+ vt0.z*vt0.z+ vt0.w*vt0.w;
        acc[5]  += vi.x*vt1.x + vi.y*vt1.y + vi.z*vt1.z + vi.w*vt1.w;
        acc[6]  += vt1.x*vt1.x+ vt1.y*vt1.y+ vt1.z*vt1.z+ vt1.w*vt1.w;
        acc[7]  += vt.x*vi0.x + vt.y*vi0.y + vt.z*vi0.z + vt.w*vi0.w;
        acc[8]  += vi0.x*vi0.x+ vi0.y*vi0.y+ vi0.z*vi0.z+ vi0.w*vi0.w;
        acc[9]  += vt.x*vi1.x + vt.y*vi1.y + vt.z*vi1.z + vt.w*vi1.w;
        acc[10] += vi1.x*vi1.x+ vi1.y*vi1.y+ vi1.z*vi1.z+ vi1.w*vi1.w;
    }

    // single warp-level reduction per row
    #pragma unroll
    for (int a = 0; a < NACC; a++) {
        float x = acc[a];
        #pragma unroll
        for (int off = 16; off > 0; off >>= 1)
            x += __shfl_xor_sync(0xFFFFFFFFu, x, off);
        acc[a] = x;
    }

    __shared__ float sloss[WARPS_PER_BLOCK];

    if (lane == 0) {
        const float ni    = sqrtf(acc[0]);   // |img_b|
        const float nt    = sqrtf(acc[1]);   // |txt_b|
        const float nprod = ni * nt;

        const float sim      = acc[2] / nprod;                      // unclamped
        const float pos_dist = 1.0f - acc[2] / fmaxf(nprod, EPSF);  // clamped

        const float dT0 = 1.0f - acc[3] / fmaxf(ni * sqrtf(acc[4]), EPSF);
        const float dT1 = 1.0f - acc[5] / fmaxf(ni * sqrtf(acc[6]), EPSF);
        const float i2t_neg = fminf(dT0, dT1);   // `d1<=d0` tie-break == min

        const float dI0 = 1.0f - acc[7] / fmaxf(nt * sqrtf(acc[8]),  EPSF);
        const float dI1 = 1.0f - acc[9] / fmaxf(nt * sqrtf(acc[10]), EPSF);
        const float t2i_neg = fminf(dI0, dI1);

        const float i2t_trip = fmaxf(pos_dist - i2t_neg + MARGIN, 0.0f);
        const float t2i_trip = fmaxf(pos_dist - t2i_neg + MARGIN, 0.0f);

        // outputs: [loss, i2t_cosine(B), t2i_cosine(B)]; cosines identical pair.
        // out[1+...] never conflicts with init (init touches only out[0]).
        out[1 + b]      = sim;
        out[1 + BB + b] = sim;
        sloss[warp] = (i2t_trip + t2i_trip) * (1.0f / (float)BB);
    }

    __syncthreads();
    if (tid == 0) {
        float s = 0.0f;
        #pragma unroll
        for (int w = 0; w < WARPS_PER_BLOCK; w++) s += sloss[w];
        // PDL: wait for init_out_kernel (which zeroes out[0]) only here,
        // after ~10us of loads/compute have already overlapped it.
        cudaGridDependencySynchronize();
        atomicAdd(out, s);   // 512 same-address atomics total
    }
}

extern "C" void kernel_launch(void* const* d_in, const int* in_sizes, int n_in,
                              void* d_out, int out_size) {
    const float* img      = (const float*)d_in[0];
    const float* txt      = (const float*)d_in[1];
    // d_in[2] = labels (identity anchors, unused), d_in[3] = locations (unused)
    const int*   cand_img = (const int*)d_in[4];
    const int*   cand_txt = (const int*)d_in[5];
    float* out = (float*)d_out;

    init_out_kernel<<<1, 1>>>(out);

    // launch main kernel with programmatic dependent launch: it may begin
    // executing while init_out_kernel is still in flight; ordering on out[0]
    // is enforced by cudaGridDependencySynchronize() before the atomics.
    cudaLaunchConfig_t cfg = {};
    cfg.gridDim  = dim3(NBLOCKS, 1, 1);
    cfg.blockDim = dim3(THREADS, 1, 1);
    cfg.dynamicSmemBytes = 0;
    cfg.stream = 0;
    cudaLaunchAttribute attrs[1];
    attrs[0].id = cudaLaunchAttributeProgrammaticStreamSerialization;
    attrs[0].val.programmaticStreamSerializationAllowed = 1;
    cfg.attrs = attrs;
    cfg.numAttrs = 1;
    cudaLaunchKernelEx(&cfg, contrastive_kernel, img, txt, cand_img, cand_txt, out);
}